// round 2
// baseline (speedup 1.0000x reference)
#include <cuda_runtime.h>
#include <math.h>

#define BB 64
#define QQ 1000
#define DD 512
#define CC 81
#define NK 80
#define KB 5
#define MK 5
#define BQ 64000          // BB*QQ
#define JJ 400            // NK*KB boundary slots per batch
#define DELTA 0.6f

// ---------------- scratch (device globals; no allocations allowed) ----------------
__device__ float g_inv[BQ];          // 1/max(||obj_row||,1e-12)
__device__ float g_invtau[BQ];       // inv * (1/TAU)
__device__ float g_dist2[BQ];        // squared dist to own prototype (matched rows)
__device__ float g_proto_n[CC * DD]; // normalized prototypes
__device__ float g_p2[NK];           // ||proto_k||^2 (raw)
__device__ int   g_mlist[BQ];        // compacted matched row ids (global n)
__device__ int   g_mcnt;
__device__ int   g_ulist[BB * 1024]; // per-batch compacted unmatched row ids
__device__ int   g_ucnt[BB];
__device__ int   g_bnd_gemm[BB * JJ];          // boundary row id (global n), safe default
__device__ unsigned char g_bnd_valid[BB * JJ];
__device__ float g_SIM[BB * JJ * QQ];          // 102.4 MB sim scratch
__device__ int   g_nb[BB * JJ * MK];           // neighbor row ids (global n)
__device__ int   g_nbcnt[BB * JJ];
__device__ unsigned char g_sgv[BB * JJ];
__device__ float g_Sm[BQ * CC];                // S rows for matched list (20.7 MB)
__device__ float g_posexp[BQ];
__device__ float g_colsum[CC];
__device__ float g_possum[CC];
__device__ float g_pneg[CC];
__device__ double g_sul_sum;
__device__ double g_cec_sum;
__device__ int    g_nsg;

// ---------------- kernels ----------------
__global__ void k_init() {
    int t = threadIdx.x;
    if (t == 0) { g_mcnt = 0; g_nsg = 0; g_sul_sum = 0.0; g_cec_sum = 0.0; }
    if (t < BB) g_ucnt[t] = 0;
    if (t < CC) { g_colsum[t] = 0.0f; g_possum[t] = 0.0f; }
}

// normalize prototypes + raw squared norms
__global__ void k_proto(const float* __restrict__ protos) {
    int c = blockIdx.x, t = threadIdx.x;
    const float* row = protos + (size_t)c * DD;
    float s = 0.0f;
    for (int i = t; i < DD; i += 128) { float v = row[i]; s += v * v; }
    for (int o = 16; o; o >>= 1) s += __shfl_xor_sync(0xffffffffu, s, o);
    __shared__ float ws[4];
    if ((t & 31) == 0) ws[t >> 5] = s;
    __syncthreads();
    __shared__ float sinv;
    if (t == 0) {
        float tot = ws[0] + ws[1] + ws[2] + ws[3];
        if (c < NK) g_p2[c] = tot;
        sinv = 1.0f / fmaxf(sqrtf(tot), 1e-12f);
    }
    __syncthreads();
    float inv = sinv;
    for (int i = t; i < DD; i += 128) g_proto_n[(size_t)c * DD + i] = row[i] * inv;
}

// per-row: inverse norms, matched-distance to own prototype, list compaction
__global__ void k_rows(const float* __restrict__ obj, const int* __restrict__ labels,
                       const float* __restrict__ protos) {
    int gw = (blockIdx.x * blockDim.x + threadIdx.x) >> 5;
    int lane = threadIdx.x & 31;
    if (gw >= BQ) return;
    const float* row = obj + (size_t)gw * DD;
    float s = 0.0f;
#pragma unroll
    for (int i = 0; i < 16; i++) { float v = row[lane + i * 32]; s += v * v; }
    for (int o = 16; o; o >>= 1) s += __shfl_xor_sync(0xffffffffu, s, o);
    float inv = 1.0f / fmaxf(sqrtf(s), 1e-12f);
    if (lane == 0) { g_inv[gw] = inv; g_invtau[gw] = inv * 10.0f; }
    int lab = labels[gw];
    if (lab < NK) {
        const float* pr = protos + (size_t)lab * DD;
        float d = 0.0f;
#pragma unroll
        for (int i = 0; i < 16; i++) d += row[lane + i * 32] * pr[lane + i * 32];
        for (int o = 16; o; o >>= 1) d += __shfl_xor_sync(0xffffffffu, d, o);
        if (lane == 0) {
            g_dist2[gw] = s - 2.0f * d + g_p2[lab];
            int slot = atomicAdd(&g_mcnt, 1);
            g_mlist[slot] = gw;
        }
    } else if (lane == 0) {
        int b = gw / QQ;
        int slot = atomicAdd(&g_ucnt[b], 1);
        g_ulist[b * 1024 + slot] = gw;
    }
}

// per (b,k): top-5 matched queries by squared distance (descending, strict > == jax tie rule)
__global__ void k_bnd(const int* __restrict__ labels) {
    int t = blockIdx.x * blockDim.x + threadIdx.x;
    if (t >= BB * NK) return;
    int b = t / NK, k = t % NK;
    const int* lb = labels + b * QQ;
    float v0 = -1.f, v1 = -1.f, v2 = -1.f, v3 = -1.f, v4 = -1.f;
    int q0 = -1, q1 = -1, q2 = -1, q3 = -1, q4 = -1;
    for (int q = 0; q < QQ; q++) {
        if (lb[q] != k) continue;
        float d = g_dist2[b * QQ + q];
        if (d > v0)      { v4=v3;q4=q3; v3=v2;q3=q2; v2=v1;q2=q1; v1=v0;q1=q0; v0=d;q0=q; }
        else if (d > v1) { v4=v3;q4=q3; v3=v2;q3=q2; v2=v1;q2=q1; v1=d;q1=q; }
        else if (d > v2) { v4=v3;q4=q3; v3=v2;q3=q2; v2=d;q2=q; }
        else if (d > v3) { v4=v3;q4=q3; v3=d;q3=q; }
        else if (d > v4) { v4=d;q4=q; }
    }
    int base = (b * NK + k) * KB;
    int qs[5] = {q0, q1, q2, q3, q4};
#pragma unroll
    for (int i = 0; i < 5; i++) {
        g_bnd_valid[base + i] = (qs[i] >= 0) ? 1 : 0;
        g_bnd_gemm[base + i] = b * QQ + (qs[i] >= 0 ? qs[i] : 0);
    }
}

// generic gather A·B^T GEMM, 64x64x16 tiles, micro 4x4.
// mode 0: SIM[b][j][u] = <obj[bnd_j], obj[u]> * inv*inv   (z = batch)
// mode 1: Sm[m][c]     = <obj[mlist_m], proto_n[c]> * inv/TAU
__global__ void __launch_bounds__(256) k_gemm(int mode, const float* __restrict__ obj) {
    const float* A; const float* Bm;
    const int* Aidx; const int* Bidx;
    int aStride, bStride, M, N, ldc;
    const float* rs; const float* cs;
    float* C; size_t zstr;
    int z = blockIdx.z;
    if (mode == 0) {
        A = obj; Bm = obj; Aidx = g_bnd_gemm; Bidx = g_ulist;
        aStride = JJ; bStride = 1024; M = JJ; N = g_ucnt[z];
        rs = g_inv; cs = g_inv; C = g_SIM; ldc = QQ; zstr = (size_t)JJ * QQ;
    } else {
        A = obj; Bm = g_proto_n; Aidx = g_mlist; Bidx = 0;
        aStride = 0; bStride = 0; M = g_mcnt; N = CC;
        rs = g_invtau; cs = 0; C = g_Sm; ldc = CC; zstr = 0;
    }
    int m0 = blockIdx.x * 64, n0 = blockIdx.y * 64;
    if (m0 >= M || n0 >= N) return;

    __shared__ __align__(16) float As[16][68];
    __shared__ __align__(16) float Bs[16][68];
    __shared__ int aid[64], bid[64];
    int tid = threadIdx.x;
    if (tid < 64) {
        int r = m0 + tid;
        aid[tid] = (r < M) ? (Aidx ? Aidx[z * aStride + r] : r) : 0;
    } else if (tid < 128) {
        int c = n0 + tid - 64;
        bid[tid - 64] = (c < N) ? (Bidx ? Bidx[z * bStride + c] : c) : 0;
    }
    __syncthreads();

    float acc[4][4];
#pragma unroll
    for (int i = 0; i < 4; i++)
#pragma unroll
        for (int j = 0; j < 4; j++) acc[i][j] = 0.0f;

    int ty = tid >> 4, tx = tid & 15;
    for (int k0 = 0; k0 < DD; k0 += 16) {
#pragma unroll
        for (int i = 0; i < 4; i++) {
            int idx = tid + i * 256;
            int d = idx & 15, r = idx >> 4;
            As[d][r] = A[(size_t)aid[r] * DD + k0 + d];
            Bs[d][r] = Bm[(size_t)bid[r] * DD + k0 + d];
        }
        __syncthreads();
#pragma unroll
        for (int d = 0; d < 16; d++) {
            float4 av4 = *(const float4*)&As[d][ty * 4];
            float4 bv4 = *(const float4*)&Bs[d][tx * 4];
            float av[4] = {av4.x, av4.y, av4.z, av4.w};
            float bv[4] = {bv4.x, bv4.y, bv4.z, bv4.w};
#pragma unroll
            for (int i = 0; i < 4; i++)
#pragma unroll
                for (int j = 0; j < 4; j++) acc[i][j] += av[i] * bv[j];
        }
        __syncthreads();
    }
#pragma unroll
    for (int i = 0; i < 4; i++) {
        int r = m0 + ty * 4 + i;
        if (r >= M) continue;
        float rv = rs ? rs[aid[ty * 4 + i]] : 1.0f;
        size_t rowoff = (size_t)z * zstr + (size_t)r * ldc;
#pragma unroll
        for (int j = 0; j < 4; j++) {
            int c = n0 + tx * 4 + j;
            if (c < N) {
                float cv = cs ? cs[bid[tx * 4 + j]] : 1.0f;
                C[rowoff + c] = acc[i][j] * rv * cv;
            }
        }
    }
}

// per (b,j): top-5 sims over unmatched queries, neighbor count, sg_valid
__global__ void k_simtop() {
    int t = blockIdx.x * blockDim.x + threadIdx.x;
    if (t >= BB * JJ) return;
    int b = t / JJ;
    const float* srow = g_SIM + (size_t)t * QQ;
    int U = g_ucnt[b];
    const int* ul = g_ulist + b * 1024;
    float v0 = -2.f, v1 = -2.f, v2 = -2.f, v3 = -2.f, v4 = -2.f;
    int n0 = -1, n1 = -1, n2 = -1, n3 = -1, n4 = -1;
    for (int u = 0; u < U; u++) {
        float s = srow[u];
        if (s <= v4) continue;
        int id = ul[u];
        if (s > v0)      { v4=v3;n4=n3; v3=v2;n3=n2; v2=v1;n2=n1; v1=v0;n1=n0; v0=s;n0=id; }
        else if (s > v1) { v4=v3;n4=n3; v3=v2;n3=n2; v2=v1;n2=n1; v1=s;n1=id; }
        else if (s > v2) { v4=v3;n4=n3; v3=v2;n3=n2; v2=s;n2=id; }
        else if (s > v3) { v4=v3;n4=n3; v3=s;n3=id; }
        else             { v4=s;n4=id; }
    }
    int cnt = (v0 > DELTA) + (v1 > DELTA) + (v2 > DELTA) + (v3 > DELTA) + (v4 > DELTA);
    g_nbcnt[t] = cnt;
    int* nb = g_nb + t * MK;
    nb[0] = n0; nb[1] = n1; nb[2] = n2; nb[3] = n3; nb[4] = n4;
    g_sgv[t] = (g_bnd_valid[t] && cnt > 0) ? 1 : 0;
}

// gated: g_bar -> logits -> CE, only for sg_valid slots (expected: none)
__global__ void k_ce(const float* __restrict__ obj, const float* __restrict__ cls_w,
                     const float* __restrict__ cls_b) {
    int bj = blockIdx.x;
    if (!g_sgv[bj]) return;
    int t = threadIdx.x;
    __shared__ float gb[DD];
    __shared__ float lg[CC];
    int cnt = g_nbcnt[bj];
    float idn = 1.0f / (1.0f + (float)cnt);
    const int* nb = g_nb + bj * MK;
    int bnd = g_bnd_gemm[bj];
    for (int d = t; d < DD; d += 128) {
        float s = obj[(size_t)bnd * DD + d];
        for (int i = 0; i < cnt; i++) s += obj[(size_t)nb[i] * DD + d];
        gb[d] = s * idn;
    }
    __syncthreads();
    if (t < CC) {
        float a = cls_b[t];
        const float* w = cls_w + (size_t)t * DD;
        for (int d = 0; d < DD; d++) a += gb[d] * w[d];
        lg[t] = a;
    }
    __syncthreads();
    if (t == 0) {
        float mx = lg[0];
        for (int c = 1; c < CC; c++) mx = fmaxf(mx, lg[c]);
        float se = 0.0f;
        for (int c = 0; c < CC; c++) se += expf(lg[c] - mx);
        float ce = mx + logf(se) - lg[CC - 1];
        atomicAdd(&g_sul_sum, (double)ce);
        atomicAdd(&g_nsg, 1);
    }
}

// exp(S) column/positive sums over matched rows + per-row pos_exp
__global__ void k_cecred(const int* __restrict__ labels) {
    __shared__ float scol[CC], spos[CC];
    int t = threadIdx.x;
    if (t < CC) { scol[t] = 0.0f; spos[t] = 0.0f; }
    __syncthreads();
    int m = blockIdx.x * 256 + t;
    int M = g_mcnt;
    bool act = m < M;
    int n = act ? g_mlist[m] : 0;
    int lab = act ? labels[n] : 0;
    const float* srow = g_Sm + (size_t)m * CC;
    int lane = t & 31;
    for (int c = 0; c < CC; c++) {
        float e = act ? expf(srow[c]) : 0.0f;
        for (int o = 16; o; o >>= 1) e += __shfl_xor_sync(0xffffffffu, e, o);
        if (lane == 0) atomicAdd(&scol[c], e);
    }
    if (act) {
        float pe = expf(srow[lab]);
        g_posexp[m] = pe;
        atomicAdd(&spos[lab], pe);
    }
    __syncthreads();
    if (t < CC) { atomicAdd(&g_colsum[t], scol[t]); atomicAdd(&g_possum[t], spos[t]); }
}

// p_neg[c] = sum_{c'!=c} exp(<proto_n[c'],proto_n[c]>/TAU)
__global__ void k_pneg() {
    int c2 = blockIdx.x;
    int t = threadIdx.x, lane = t & 31, w = t >> 5;
    const float* pb = g_proto_n + (size_t)c2 * DD;
    __shared__ float acc;
    if (t == 0) acc = 0.0f;
    __syncthreads();
    float local = 0.0f;
    for (int c1 = w; c1 < CC; c1 += 8) {
        if (c1 == c2) continue;
        const float* pa = g_proto_n + (size_t)c1 * DD;
        float d = 0.0f;
#pragma unroll
        for (int i = 0; i < 16; i++) d += pa[lane + i * 32] * pb[lane + i * 32];
        for (int o = 16; o; o >>= 1) d += __shfl_xor_sync(0xffffffffu, d, o);
        if (lane == 0) local += expf(d * 10.0f);
    }
    if (lane == 0) atomicAdd(&acc, local);
    __syncthreads();
    if (t == 0) g_pneg[c2] = acc;
}

__global__ void k_loss(const int* __restrict__ labels) {
    int t = threadIdx.x;
    int m = blockIdx.x * 256 + t;
    float l = 0.0f;
    if (m < g_mcnt) {
        int n = g_mlist[m];
        int lab = labels[n];
        float E = g_pneg[lab] + g_colsum[lab] - g_possum[lab];
        float pe = g_posexp[m];
        l = -logf(pe / (pe + E + 1e-8f));
    }
    for (int o = 16; o; o >>= 1) l += __shfl_xor_sync(0xffffffffu, l, o);
    if ((t & 31) == 0) atomicAdd(&g_cec_sum, (double)l);
}

__global__ void k_fin(float* __restrict__ out) {
    int nsg = g_nsg;
    out[0] = (nsg > 0) ? (float)(g_sul_sum / (double)nsg) : 0.0f;
    int mc = g_mcnt;
    out[1] = (mc > 0) ? (float)(g_cec_sum / (double)mc) : 0.0f;
}

// ---------------- launcher ----------------
extern "C" void kernel_launch(void* const* d_in, const int* in_sizes, int n_in,
                              void* d_out, int out_size) {
    const float* obj    = (const float*)d_in[0];
    const float* protos = (const float*)d_in[1];
    const float* cls_w  = (const float*)d_in[2];
    const float* cls_b  = (const float*)d_in[3];
    const int*   labels = (const int*)d_in[4];
    float* out = (float*)d_out;

    k_init<<<1, 256>>>();
    k_proto<<<CC, 128>>>(protos);
    k_rows<<<BQ / 8, 256>>>(obj, labels, protos);            // 8 warps/block -> 64000 warps
    k_bnd<<<(BB * NK + 127) / 128, 128>>>(labels);
    k_gemm<<<dim3(7, 16, BB), 256>>>(0, obj);                // SIM
    k_gemm<<<dim3((BQ + 63) / 64, 2, 1), 256>>>(1, obj);     // S (matched rows x 81)
    k_simtop<<<(BB * JJ + 127) / 128, 128>>>();
    k_ce<<<BB * JJ, 128>>>(obj, cls_w, cls_b);
    k_cecred<<<BQ / 256, 256>>>(labels);
    k_pneg<<<CC, 256>>>();
    k_loss<<<BQ / 256, 256>>>(labels);
    k_fin<<<1, 1>>>(out);
}

// round 6
// speedup vs baseline: 2.3539x; 2.3539x over previous
#include <cuda_runtime.h>
#include <cuda_bf16.h>
#include <math.h>
#include <stdint.h>

#define BB 64
#define QQ 1000
#define DD 512
#define CC 81
#define NK 80
#define KB 5
#define MK 5
#define BQ 64000          // BB*QQ
#define JJ 400            // NK*KB boundary slots per batch
#define DELTA 0.6f

// ---------------- scratch (device globals; no allocations allowed) ----------------
__device__ uint4 g_embn4[(size_t)BQ * (DD / 8)];     // normalized embeddings, bf16 (65.5 MB)
__device__ uint4 g_protonb4[CC * (DD / 8)];          // normalized prototypes, bf16
__device__ float g_dist2[BQ];
__device__ float g_proto_n[CC * DD];                 // normalized prototypes fp32 (k_pneg)
__device__ float g_p2[NK];
__device__ float g_pinv[CC];
__device__ int   g_mlist[BQ];
__device__ int   g_mcnt;
__device__ int   g_ulist[BB * 1024];
__device__ int   g_ucnt[BB];
__device__ int   g_bnd_gemm[BB * JJ];
__device__ unsigned char g_bnd_valid[BB * JJ];
__device__ float g_SIM[(size_t)BB * JJ * QQ];        // 102.4 MB
__device__ int   g_nb[BB * JJ * MK];
__device__ int   g_nbcnt[BB * JJ];
__device__ unsigned char g_sgv[BB * JJ];
__device__ float g_Sm[(size_t)BQ * CC];              // exp(S) for matched rows (20.7 MB)
__device__ float g_posexp[BQ];                       // fp32-exact pos exp, per row n
__device__ float g_colsum[CC];
__device__ float g_possum[CC];
__device__ float g_pneg[CC];
__device__ double g_sul_sum;
__device__ double g_cec_sum;
__device__ int    g_nsg;

// ---------------- helpers ----------------
__device__ __forceinline__ uint32_t smem_u32(const void* p) {
    uint32_t a;
    asm("{ .reg .u64 t; cvta.to.shared.u64 t, %1; cvt.u32.u64 %0, t; }" : "=r"(a) : "l"(p));
    return a;
}
__device__ __forceinline__ void ldsm_x4(uint32_t& r0, uint32_t& r1, uint32_t& r2, uint32_t& r3,
                                        uint32_t addr) {
    asm volatile("ldmatrix.sync.aligned.m8n8.x4.shared.b16 {%0,%1,%2,%3}, [%4];"
                 : "=r"(r0), "=r"(r1), "=r"(r2), "=r"(r3) : "r"(addr));
}
__device__ __forceinline__ void mma_16816(float* c, const uint32_t* a, uint32_t b0, uint32_t b1) {
    asm volatile(
        "mma.sync.aligned.m16n8k16.row.col.f32.bf16.bf16.f32 "
        "{%0,%1,%2,%3}, {%4,%5,%6,%7}, {%8,%9}, {%0,%1,%2,%3};"
        : "+f"(c[0]), "+f"(c[1]), "+f"(c[2]), "+f"(c[3])
        : "r"(a[0]), "r"(a[1]), "r"(a[2]), "r"(a[3]), "r"(b0), "r"(b1));
}

// ---------------- warp-cooperative top-5 (stable: value desc, index asc) ----------------
__device__ __forceinline__ void lane_ins5(float* v, int* ix, float s, int q) {
    if (s <= v[4]) return;
    int p = 4;
#pragma unroll
    for (int j = 3; j >= 0; j--) if (s > v[j]) p = j;
#pragma unroll
    for (int j = 4; j > 0; j--) if (j > p) { v[j] = v[j - 1]; ix[j] = ix[j - 1]; }
    v[p] = s; ix[p] = q;
}
__device__ __forceinline__ void warp_merge5(float* v, int* ix, float* ov, int* oi) {
#pragma unroll
    for (int r = 0; r < 5; r++) {
        float bv = v[0]; int bi = ix[0];
#pragma unroll
        for (int o = 16; o; o >>= 1) {
            float tv = __shfl_xor_sync(0xffffffffu, bv, o);
            int   ti = __shfl_xor_sync(0xffffffffu, bi, o);
            if (tv > bv || (tv == bv && ti < bi)) { bv = tv; bi = ti; }
        }
        ov[r] = bv; oi[r] = bi;
        if (ix[0] == bi && bi != 0x7fffffff) {
#pragma unroll
            for (int j = 0; j < 4; j++) { v[j] = v[j + 1]; ix[j] = ix[j + 1]; }
            v[4] = -INFINITY; ix[4] = 0x7fffffff;
        }
    }
}

// ---------------- kernels ----------------
__global__ void k_init() {
    int t = threadIdx.x;
    if (t == 0) { g_mcnt = 0; g_nsg = 0; g_sul_sum = 0.0; g_cec_sum = 0.0; }
    if (t < BB) g_ucnt[t] = 0;
    if (t < CC) { g_colsum[t] = 0.0f; g_possum[t] = 0.0f; }
}

__global__ void k_proto(const float* __restrict__ protos) {
    int c = blockIdx.x, t = threadIdx.x;
    const float* row = protos + (size_t)c * DD;
    float s = 0.0f;
    for (int i = t; i < DD; i += 128) { float v = row[i]; s += v * v; }
    for (int o = 16; o; o >>= 1) s += __shfl_xor_sync(0xffffffffu, s, o);
    __shared__ float ws[4];
    if ((t & 31) == 0) ws[t >> 5] = s;
    __syncthreads();
    __shared__ float sinv;
    if (t == 0) {
        float tot = ws[0] + ws[1] + ws[2] + ws[3];
        if (c < NK) g_p2[c] = tot;
        float inv = 1.0f / fmaxf(sqrtf(tot), 1e-12f);
        g_pinv[c] = inv;
        sinv = inv;
    }
    __syncthreads();
    float inv = sinv;
    const float2* r2 = (const float2*)row;
    uint32_t* pb = (uint32_t*)g_protonb4 + c * (DD / 2);
    for (int i = t; i < DD / 2; i += 128) {
        float2 f = r2[i];
        float x = f.x * inv, y = f.y * inv;
        g_proto_n[c * DD + 2 * i] = x;
        g_proto_n[c * DD + 2 * i + 1] = y;
        __nv_bfloat162 h = __floats2bfloat162_rn(x, y);
        pb[i] = *(uint32_t*)&h;
    }
}

// warp per row: norm, bf16 normalized copy, matched dist + exact fp32 pos_exp, compaction
__global__ void k_rows(const float* __restrict__ obj, const int* __restrict__ labels,
                       const float* __restrict__ protos) {
    int gw = (blockIdx.x * blockDim.x + threadIdx.x) >> 5;
    int lane = threadIdx.x & 31;
    if (gw >= BQ) return;
    const float2* row = (const float2*)(obj + (size_t)gw * DD);
    float2 v[8];
    float s = 0.0f;
#pragma unroll
    for (int i = 0; i < 8; i++) { v[i] = row[lane + 32 * i]; s += v[i].x * v[i].x + v[i].y * v[i].y; }
#pragma unroll
    for (int o = 16; o; o >>= 1) s += __shfl_xor_sync(0xffffffffu, s, o);
    float inv = 1.0f / fmaxf(sqrtf(s), 1e-12f);
    uint32_t* eb = (uint32_t*)g_embn4 + (size_t)gw * (DD / 2);
#pragma unroll
    for (int i = 0; i < 8; i++) {
        __nv_bfloat162 h = __floats2bfloat162_rn(v[i].x * inv, v[i].y * inv);
        eb[lane + 32 * i] = *(uint32_t*)&h;
    }
    int lab = labels[gw];
    if (lab < NK) {
        const float2* pr = (const float2*)(protos + (size_t)lab * DD);
        float d = 0.0f;
#pragma unroll
        for (int i = 0; i < 8; i++) { float2 p = pr[lane + 32 * i]; d += v[i].x * p.x + v[i].y * p.y; }
#pragma unroll
        for (int o = 16; o; o >>= 1) d += __shfl_xor_sync(0xffffffffu, d, o);
        if (lane == 0) {
            g_dist2[gw] = s - 2.0f * d + g_p2[lab];
            g_posexp[gw] = expf(d * inv * g_pinv[lab] * 10.0f);   // exact fp32 S_pos
            int slot = atomicAdd(&g_mcnt, 1);
            g_mlist[slot] = gw;
        }
    } else if (lane == 0) {
        int b = gw / QQ;
        int slot = atomicAdd(&g_ucnt[b], 1);
        g_ulist[b * 1024 + slot] = gw;
    }
}

// warp per (b,k): top-5 matched distances
__global__ void k_bnd(const int* __restrict__ labels) {
    int gw = (blockIdx.x * blockDim.x + threadIdx.x) >> 5;
    int lane = threadIdx.x & 31;
    if (gw >= BB * NK) return;
    int b = gw / NK, k = gw - b * NK;
    const int* lb = labels + b * QQ;
    const float* dd = g_dist2 + b * QQ;
    float v[5] = {-INFINITY, -INFINITY, -INFINITY, -INFINITY, -INFINITY};
    int ix[5] = {0x7fffffff, 0x7fffffff, 0x7fffffff, 0x7fffffff, 0x7fffffff};
    for (int q = lane; q < QQ; q += 32)
        if (lb[q] == k) lane_ins5(v, ix, dd[q], q);
    float ov[5]; int oi[5];
    warp_merge5(v, ix, ov, oi);
    if (lane == 0) {
        int base = gw * KB;
#pragma unroll
        for (int i = 0; i < 5; i++) {
            bool valid = oi[i] != 0x7fffffff;
            g_bnd_valid[base + i] = valid ? 1 : 0;
            g_bnd_gemm[base + i] = b * QQ + (valid ? oi[i] : 0);
        }
    }
}

// ---------------- bf16 HMMA gather-GEMM: 128x64 tiles, K=512 in 8 chunks of 64 ----------------
// mode 0: SIM[z][m][u] = <embn[bnd], embn[ulist]>        grid (4, 16, 64)
// mode 1: Sm[m][c]     = exp(10 * <embn[mlist], proton>)  grid (ceil(M/128), 2, 1)
// smem: [0,512) aid  [512,768) bid  [1024,+18432) As(128x72bf16)  [19456,+9216) Bs(64x72)
// epilogue mode0 reuses [1024, +33792) as float[128][66]
#define ASTRIDE 144              // 72 bf16 per row
__global__ void __launch_bounds__(256) k_tgemm(int mode) {
    extern __shared__ unsigned char smem[];
    const int tid = threadIdx.x, wid = tid >> 5, lid = tid & 31;
    const int wm = wid & 3, wn = wid >> 2;           // warp tile: rows wm*32, cols wn*32
    const int z = blockIdx.z;
    const int m0 = blockIdx.x * 128, n0 = blockIdx.y * 64;
    int M, N;
    const uint4 *Asrc, *Bsrc;
    if (mode == 0) {
        M = JJ; N = g_ucnt[z];
        if (n0 >= N) return;
        Asrc = g_embn4; Bsrc = g_embn4;
    } else {
        M = g_mcnt; N = CC;
        if (m0 >= M) return;
        Asrc = g_embn4; Bsrc = g_protonb4;
    }
    int* aid = (int*)smem;
    int* bid = (int*)(smem + 512);
    uint32_t sbase = smem_u32(smem);
    if (tid < 128) {
        int r = m0 + tid;
        int a;
        if (mode == 0) a = g_bnd_gemm[z * JJ + (r < JJ ? r : 0)];
        else a = (r < M) ? g_mlist[r] : g_mlist[0];
        aid[tid] = a;
    } else if (tid < 192) {
        int c = n0 + tid - 128, b0;
        if (mode == 0) b0 = (c < N) ? g_ulist[z * 1024 + c] : g_ulist[z * 1024];
        else b0 = (c < N) ? c : 0;
        bid[tid - 128] = b0;
    }
    __syncthreads();

    // per-lane ldmatrix address components
    const uint32_t As0 = sbase + 1024, Bs0 = sbase + 19456;
    uint32_t aAddr = As0 + (uint32_t)(wm * 32 + (lid & 15)) * ASTRIDE + ((lid >> 4) * 8) * 2;
    uint32_t bAddr = Bs0 + (uint32_t)(wn * 32 + ((lid & 7) | ((lid >> 4) << 3))) * ASTRIDE
                         + (((lid >> 3) & 1) * 8) * 2;

    float acc[2][4][4];
#pragma unroll
    for (int i = 0; i < 2; i++)
#pragma unroll
        for (int j = 0; j < 4; j++)
#pragma unroll
            for (int e = 0; e < 4; e++) acc[i][j][e] = 0.0f;

    for (int ch = 0; ch < 8; ch++) {
#pragma unroll
        for (int i = 0; i < 4; i++) {          // A: 128 rows x 8 uint4
            int idx = tid + i * 256, r = idx >> 3, j = idx & 7;
            uint4 vv = Asrc[(size_t)aid[r] * 64 + ch * 8 + j];
            *(uint4*)(smem + 1024 + r * ASTRIDE + j * 16) = vv;
        }
#pragma unroll
        for (int i = 0; i < 2; i++) {          // B: 64 rows x 8 uint4
            int idx = tid + i * 256, r = idx >> 3, j = idx & 7;
            uint4 vv = Bsrc[(size_t)bid[r] * 64 + ch * 8 + j];
            *(uint4*)(smem + 19456 + r * ASTRIDE + j * 16) = vv;
        }
        __syncthreads();
#pragma unroll
        for (int ks = 0; ks < 4; ks++) {
            uint32_t a[2][4], b[2][4];
#pragma unroll
            for (int mt = 0; mt < 2; mt++)
                ldsm_x4(a[mt][0], a[mt][1], a[mt][2], a[mt][3],
                        aAddr + mt * 16 * ASTRIDE + ks * 32);
#pragma unroll
            for (int nh = 0; nh < 2; nh++)
                ldsm_x4(b[nh][0], b[nh][1], b[nh][2], b[nh][3],
                        bAddr + nh * 16 * ASTRIDE + ks * 32);
#pragma unroll
            for (int mt = 0; mt < 2; mt++)
#pragma unroll
                for (int nt = 0; nt < 4; nt++) {
                    int nh = nt >> 1, hi = (nt & 1) << 1;
                    mma_16816(acc[mt][nt], a[mt], b[nh][hi], b[nh][hi + 1]);
                }
        }
        __syncthreads();
    }

    if (mode == 0) {
        // transpose through padded smem -> coalesced float2 global stores
        float* sD = (float*)(smem + 1024);     // 128 x 66
#pragma unroll
        for (int mt = 0; mt < 2; mt++)
#pragma unroll
            for (int nt = 0; nt < 4; nt++)
#pragma unroll
                for (int e = 0; e < 4; e++) {
                    int row = wm * 32 + mt * 16 + (lid >> 2) + ((e >> 1) << 3);
                    int col = wn * 32 + nt * 8 + (lid & 3) * 2 + (e & 1);
                    sD[row * 66 + col] = acc[mt][nt][e];
                }
        __syncthreads();
#pragma unroll
        for (int i = 0; i < 16; i++) {
            int idx = tid + i * 256, r = idx >> 5, j = idx & 31;
            int gr = m0 + r, col = n0 + j * 2;
            if (gr < JJ && col < N) {
                float2 val = *(float2*)&sD[r * 66 + j * 2];
                float* dst = g_SIM + ((size_t)(z * JJ + gr)) * QQ + col;
                if (col + 1 < N) *(float2*)dst = val;
                else dst[0] = val.x;
            }
        }
    } else {
        // direct store with fused exp(10*x)
#pragma unroll
        for (int mt = 0; mt < 2; mt++)
#pragma unroll
            for (int nt = 0; nt < 4; nt++)
#pragma unroll
                for (int e = 0; e < 4; e++) {
                    int gr = m0 + wm * 32 + mt * 16 + (lid >> 2) + ((e >> 1) << 3);
                    int col = n0 + wn * 32 + nt * 8 + (lid & 3) * 2 + (e & 1);
                    if (gr < M && col < N)
                        g_Sm[(size_t)gr * CC + col] = expf(acc[mt][nt][e] * 10.0f);
                }
    }
}

// warp per (b,j): top-5 sims over unmatched, neighbor count, sg_valid
__global__ void k_simtop() {
    int gw = (blockIdx.x * blockDim.x + threadIdx.x) >> 5;
    int lane = threadIdx.x & 31;
    if (gw >= BB * JJ) return;
    int b = gw / JJ;
    const float* srow = g_SIM + (size_t)gw * QQ;
    int U = g_ucnt[b];
    const int* ul = g_ulist + b * 1024;
    float v[5] = {-INFINITY, -INFINITY, -INFINITY, -INFINITY, -INFINITY};
    int ix[5] = {0x7fffffff, 0x7fffffff, 0x7fffffff, 0x7fffffff, 0x7fffffff};
    for (int u = lane; u < U; u += 32) lane_ins5(v, ix, srow[u], u);
    float ov[5]; int oi[5];
    warp_merge5(v, ix, ov, oi);
    if (lane == 0) {
        int cnt = 0;
        int* nb = g_nb + gw * MK;
#pragma unroll
        for (int i = 0; i < 5; i++) {
            bool valid = oi[i] != 0x7fffffff;
            cnt += (valid && ov[i] > DELTA) ? 1 : 0;
            nb[i] = valid ? ul[oi[i]] : -1;
        }
        g_nbcnt[gw] = cnt;
        g_sgv[gw] = (g_bnd_valid[gw] && cnt > 0) ? 1 : 0;
    }
}

// gated: g_bar -> logits -> CE (expected: no valid slots -> no work)
__global__ void k_ce(const float* __restrict__ obj, const float* __restrict__ cls_w,
                     const float* __restrict__ cls_b) {
    int bj = blockIdx.x;
    if (!g_sgv[bj]) return;
    int t = threadIdx.x;
    __shared__ float gb[DD];
    __shared__ float lg[CC];
    int cnt = g_nbcnt[bj];
    float idn = 1.0f / (1.0f + (float)cnt);
    const int* nb = g_nb + bj * MK;
    int bnd = g_bnd_gemm[bj];
    for (int d = t; d < DD; d += 128) {
        float s = obj[(size_t)bnd * DD + d];
        for (int i = 0; i < cnt; i++) s += obj[(size_t)nb[i] * DD + d];
        gb[d] = s * idn;
    }
    __syncthreads();
    if (t < CC) {
        float a = cls_b[t];
        const float* w = cls_w + (size_t)t * DD;
        for (int d = 0; d < DD; d++) a += gb[d] * w[d];
        lg[t] = a;
    }
    __syncthreads();
    if (t == 0) {
        float mx = lg[0];
        for (int c = 1; c < CC; c++) mx = fmaxf(mx, lg[c]);
        float se = 0.0f;
        for (int c = 0; c < CC; c++) se += expf(lg[c] - mx);
        float ce = mx + logf(se) - lg[CC - 1];
        atomicAdd(&g_sul_sum, (double)ce);
        atomicAdd(&g_nsg, 1);
    }
}

// column / positive sums of exp(S) over matched rows (Sm already holds expS)
__global__ void k_cecred(const int* __restrict__ labels) {
    __shared__ float scol[CC], spos[CC];
    int t = threadIdx.x;
    if (t < CC) { scol[t] = 0.0f; spos[t] = 0.0f; }
    __syncthreads();
    int m = blockIdx.x * 256 + t;
    int M = g_mcnt;
    bool act = m < M;
    int n = act ? g_mlist[m] : 0;
    int lab = act ? labels[n] : 0;
    const float* srow = g_Sm + (size_t)m * CC;
    int lane = t & 31;
    for (int c = 0; c < CC; c++) {
        float e = act ? srow[c] : 0.0f;
        for (int o = 16; o; o >>= 1) e += __shfl_xor_sync(0xffffffffu, e, o);
        if (lane == 0) atomicAdd(&scol[c], e);
    }
    if (act) atomicAdd(&spos[lab], srow[lab]);
    __syncthreads();
    if (t < CC) { atomicAdd(&g_colsum[t], scol[t]); atomicAdd(&g_possum[t], spos[t]); }
}

__global__ void k_pneg() {
    int c2 = blockIdx.x;
    int t = threadIdx.x, lane = t & 31, w = t >> 5;
    const float* pb = g_proto_n + (size_t)c2 * DD;
    __shared__ float acc;
    if (t == 0) acc = 0.0f;
    __syncthreads();
    float local = 0.0f;
    for (int c1 = w; c1 < CC; c1 += 8) {
        if (c1 == c2) continue;
        const float* pa = g_proto_n + (size_t)c1 * DD;
        float d = 0.0f;
#pragma unroll
        for (int i = 0; i < 16; i++) d += pa[lane + i * 32] * pb[lane + i * 32];
        for (int o = 16; o; o >>= 1) d += __shfl_xor_sync(0xffffffffu, d, o);
        if (lane == 0) local += expf(d * 10.0f);
    }
    if (lane == 0) atomicAdd(&acc, local);
    __syncthreads();
    if (t == 0) g_pneg[c2] = acc;
}

__global__ void k_loss(const int* __restrict__ labels) {
    int t = threadIdx.x;
    int m = blockIdx.x * 256 + t;
    float l = 0.0f;
    if (m < g_mcnt) {
        int n = g_mlist[m];
        int lab = labels[n];
        float E = g_pneg[lab] + g_colsum[lab] - g_possum[lab];
        float pe = g_posexp[n];
        l = -logf(pe / (pe + E + 1e-8f));
    }
    for (int o = 16; o; o >>= 1) l += __shfl_xor_sync(0xffffffffu, l, o);
    if ((t & 31) == 0) atomicAdd(&g_cec_sum, (double)l);
}

__global__ void k_fin(float* __restrict__ out) {
    int nsg = g_nsg;
    out[0] = (nsg > 0) ? (float)(g_sul_sum / (double)nsg) : 0.0f;
    int mc = g_mcnt;
    out[1] = (mc > 0) ? (float)(g_cec_sum / (double)mc) : 0.0f;
}

// ---------------- launcher ----------------
extern "C" void kernel_launch(void* const* d_in, const int* in_sizes, int n_in,
                              void* d_out, int out_size) {
    const float* obj    = (const float*)d_in[0];
    const float* protos = (const float*)d_in[1];
    const float* cls_w  = (const float*)d_in[2];
    const float* cls_b  = (const float*)d_in[3];
    const int*   labels = (const int*)d_in[4];
    float* out = (float*)d_out;

    const int TG_SMEM = 1024 + 128 * 66 * 4;   // 34816 B (mainloop needs 28672)

    k_init<<<1, 256>>>();
    k_proto<<<CC, 128>>>(protos);
    k_rows<<<BQ / 8, 256>>>(obj, labels, protos);
    k_bnd<<<BB * NK / 8, 256>>>(labels);
    k_tgemm<<<dim3(4, 16, BB), 256, TG_SMEM>>>(0);                 // SIM
    k_tgemm<<<dim3((BQ + 127) / 128, 2, 1), 256, TG_SMEM>>>(1);    // exp(S)
    k_simtop<<<BB * JJ / 8, 256>>>();
    k_ce<<<BB * JJ, 128>>>(obj, cls_w, cls_b);
    k_cecred<<<(BQ + 255) / 256, 256>>>(labels);
    k_pneg<<<CC, 256>>>();
    k_loss<<<(BQ + 255) / 256, 256>>>(labels);
    k_fin<<<1, 1>>>(out);
}